// round 2
// baseline (speedup 1.0000x reference)
#include <cuda_runtime.h>
#include <math.h>
#include <stdint.h>

// ---------------- problem constants ----------------
#define kB    16
#define kH    64
#define kW    64
#define kC    192
#define kHD   32
#define kNH   6
#define kP    8
#define kSH   4            // SHIFT
#define kNW   64           // (H/P)*(W/P)
#define kPP   64           // P*P
#define kTOK  (kB*kH*kW)   // 65536

// ---------------- device scratch (no allocation allowed) ----------------
__device__ float g_hwin[(size_t)kTOK * kC];        //  50 MB  LN1+windowed
__device__ float g_qkv [(size_t)kTOK * 3 * kC];    // 151 MB
__device__ float g_attn[(size_t)kTOK * kC];        //  50 MB
__device__ float g_x1  [(size_t)kTOK * kC];        //  50 MB  after attn residual
__device__ float g_h2n [(size_t)kTOK * kC];        //  50 MB  LN2 out
__device__ float g_mid [(size_t)kTOK * 4 * kC];    // 201 MB  MLP hidden
__device__ float g_btab[kNH * kPP * kPP];          // rel-pos bias table

// ---------------- relative position bias table ----------------
__global__ void btab_kernel(const float* __restrict__ rel) {
    int idx = blockIdx.x * 256 + threadIdx.x;
    if (idx >= kNH * kPP * kPP) return;
    int h = idx >> 12;
    int r = idx & 4095;
    int p = r >> 6, q = r & 63;
    int dy = (p >> 3) - (q >> 3) + (kP - 1);
    int dx = (p & 7)  - (q & 7)  + (kP - 1);
    g_btab[idx] = rel[h * (2*kP-1)*(2*kP-1) + dy * (2*kP-1) + dx];
}

// ---------------- LayerNorm kernels ----------------
// LN1: read original x with roll(-4,-4) applied, write window-partitioned g_hwin.
__global__ void ln1_kernel(const float* __restrict__ x,
                           const float* __restrict__ g,
                           const float* __restrict__ bt) {
    int t = blockIdx.x;              // rolled token index (b,i,j)
    int c = threadIdx.x;             // 0..191
    int b = t >> 12;
    int ij = t & 4095;
    int i = ij >> 6, j = ij & 63;
    int si = (i + kSH) & 63, sj = (j + kSH) & 63;   // source pixel in x
    float v = x[((size_t)(((b << 6) + si) << 6) + sj) * kC + c];

    __shared__ float red1[6], red2[6];
    int wid = c >> 5, lane = c & 31;
    float s = v;
    #pragma unroll
    for (int o = 16; o; o >>= 1) s += __shfl_xor_sync(0xffffffffu, s, o);
    if (lane == 0) red1[wid] = s;
    __syncthreads();
    float mean = (red1[0]+red1[1]+red1[2]+red1[3]+red1[4]+red1[5]) * (1.0f/kC);
    float d = v - mean;
    float q = d * d;
    #pragma unroll
    for (int o = 16; o; o >>= 1) q += __shfl_xor_sync(0xffffffffu, q, o);
    if (lane == 0) red2[wid] = q;
    __syncthreads();
    float var = (red2[0]+red2[1]+red2[2]+red2[3]+red2[4]+red2[5]) * (1.0f/kC);
    float out = d * rsqrtf(var + 1e-5f) * g[c] + bt[c];

    int wi = i >> 3, pi = i & 7, wj = j >> 3, pj = j & 7;
    int n  = (wi << 3) + wj;
    int p  = (pi << 3) + pj;
    size_t row = (size_t)((b << 6) + n) * 64 + p;
    g_hwin[row * kC + c] = out;
}

// LN2: plain token-order layernorm, reads g_x1, writes g_h2n.
__global__ void ln2_kernel(const float* __restrict__ g,
                           const float* __restrict__ bt) {
    int t = blockIdx.x;
    int c = threadIdx.x;
    float v = g_x1[(size_t)t * kC + c];

    __shared__ float red1[6], red2[6];
    int wid = c >> 5, lane = c & 31;
    float s = v;
    #pragma unroll
    for (int o = 16; o; o >>= 1) s += __shfl_xor_sync(0xffffffffu, s, o);
    if (lane == 0) red1[wid] = s;
    __syncthreads();
    float mean = (red1[0]+red1[1]+red1[2]+red1[3]+red1[4]+red1[5]) * (1.0f/kC);
    float d = v - mean;
    float q = d * d;
    #pragma unroll
    for (int o = 16; o; o >>= 1) q += __shfl_xor_sync(0xffffffffu, q, o);
    if (lane == 0) red2[wid] = q;
    __syncthreads();
    float var = (red2[0]+red2[1]+red2[2]+red2[3]+red2[4]+red2[5]) * (1.0f/kC);
    g_h2n[(size_t)t * kC + c] = d * rsqrtf(var + 1e-5f) * g[c] + bt[c];
}

// ---------------- window-reverse + roll-back row mapping ----------------
__device__ __forceinline__ int map_row(int r) {
    int b   = r >> 12;
    int rem = r & 4095;
    int n = rem >> 6, p = rem & 63;
    int wi = n >> 3, wj = n & 7;
    int pi = p >> 3, pj = p & 7;
    int i = (wi * kP + pi + kSH) & 63;   // roll(+SHIFT)
    int j = (wj * kP + pj + kSH) & 63;
    return (((b << 6) + i) << 6) + j;
}

// ---------------- SGEMM: C = A[M,K] @ W[K,N] + bias, with epilogues ----------------
// EPI 0: plain          1: GELU(exact)      2: proj (scatter via map_row + residual X0)
// EPI 3: residual add (row-aligned)
template<int EPI>
__global__ void __launch_bounds__(256) sgemm_kernel(
    const float* __restrict__ A, const float* __restrict__ Bw,
    const float* __restrict__ bias, const float* __restrict__ R,
    float* __restrict__ Co, int M, int N, int K)
{
    __shared__ float As[16][128];
    __shared__ float Bs[16][64];
    int tid = threadIdx.x;
    int bm = blockIdx.y << 7;      // 128-row tile
    int bn = blockIdx.x << 6;      // 64-col tile
    int a_row = tid >> 1, a_k = (tid & 1) << 2;     // each thread: 2 float4 of A
    int b_k = tid >> 4,  b_n = (tid & 15) << 2;     // each thread: 1 float4 of B
    int ty = tid >> 4, tx = tid & 15;

    const float* Ap = A + (size_t)(bm + a_row) * K + a_k;
    const float* Bp = Bw + (size_t)b_k * N + bn + b_n;

    float acc[8][4];
    #pragma unroll
    for (int i = 0; i < 8; i++)
        #pragma unroll
        for (int j = 0; j < 4; j++) acc[i][j] = 0.0f;

    for (int k0 = 0; k0 < K; k0 += 16) {
        float4 a0 = *(const float4*)(Ap);
        float4 a1 = *(const float4*)(Ap + 8);
        float4 bv = *(const float4*)(Bp);
        __syncthreads();   // previous compute finished before overwrite
        As[a_k + 0][a_row] = a0.x; As[a_k + 1][a_row] = a0.y;
        As[a_k + 2][a_row] = a0.z; As[a_k + 3][a_row] = a0.w;
        As[a_k + 8][a_row] = a1.x; As[a_k + 9][a_row] = a1.y;
        As[a_k +10][a_row] = a1.z; As[a_k +11][a_row] = a1.w;
        *(float4*)&Bs[b_k][b_n] = bv;
        __syncthreads();
        #pragma unroll
        for (int k = 0; k < 16; k++) {
            float4 ra0 = *(const float4*)&As[k][ty * 8];
            float4 ra1 = *(const float4*)&As[k][ty * 8 + 4];
            float4 rb  = *(const float4*)&Bs[k][tx * 4];
            float ar[8] = {ra0.x, ra0.y, ra0.z, ra0.w, ra1.x, ra1.y, ra1.z, ra1.w};
            float br[4] = {rb.x, rb.y, rb.z, rb.w};
            #pragma unroll
            for (int i = 0; i < 8; i++)
                #pragma unroll
                for (int j = 0; j < 4; j++)
                    acc[i][j] = fmaf(ar[i], br[j], acc[i][j]);
        }
        Ap += 16;
        Bp += (size_t)16 * N;
    }

    #pragma unroll
    for (int i = 0; i < 8; i++) {
        int r = bm + ty * 8 + i;
        int orow = r;
        if (EPI == 2) orow = map_row(r);
        #pragma unroll
        for (int j = 0; j < 4; j++) {
            int ccol = bn + tx * 4 + j;
            float v = acc[i][j] + bias[ccol];
            if (EPI == 1) v = 0.5f * v * (1.0f + erff(v * 0.70710678118654752f));
            if (EPI == 2) v += R[(size_t)orow * N + ccol];
            if (EPI == 3) v += R[(size_t)r * N + ccol];
            Co[(size_t)orow * N + ccol] = v;
        }
    }
}

// ---------------- windowed attention: one block per (b, window, head) ----------------
__global__ void __launch_bounds__(256) attn_kernel() {
    __shared__ float qs[64][33];
    __shared__ float ks[64][33];
    __shared__ float vs[64][33];
    __shared__ float sim[64][65];

    int tid = threadIdx.x;
    int h  = blockIdx.x % kNH;
    int bn = blockIdx.x / kNH;      // b*64 + n
    int n  = bn & 63;
    size_t rowbase = (size_t)bn * 64;

    // load Q,K,V tiles (64x32 each) from g_qkv
    #pragma unroll
    for (int it = 0; it < 2; it++) {
        int idx = tid + it * 256;          // 0..511
        int r = idx >> 3;
        int f = (idx & 7) << 2;
        const float* base = &g_qkv[(rowbase + r) * (3 * kC) + h * kHD + f];
        float4 qv = *(const float4*)(base);
        float4 kv = *(const float4*)(base + kC);
        float4 vv = *(const float4*)(base + 2 * kC);
        qs[r][f] = qv.x; qs[r][f+1] = qv.y; qs[r][f+2] = qv.z; qs[r][f+3] = qv.w;
        ks[r][f] = kv.x; ks[r][f+1] = kv.y; ks[r][f+2] = kv.z; ks[r][f+3] = kv.w;
        vs[r][f] = vv.x; vs[r][f+1] = vv.y; vs[r][f+2] = vv.z; vs[r][f+3] = vv.w;
    }
    __syncthreads();

    int ty = tid >> 4, tx = tid & 15;

    // S = Q @ K^T  (64x64, each thread 4x4)
    float acc[4][4];
    #pragma unroll
    for (int i = 0; i < 4; i++)
        #pragma unroll
        for (int j = 0; j < 4; j++) acc[i][j] = 0.0f;
    #pragma unroll
    for (int d = 0; d < 32; d++) {
        float rq[4], rk[4];
        #pragma unroll
        for (int i = 0; i < 4; i++) rq[i] = qs[ty * 4 + i][d];
        #pragma unroll
        for (int j = 0; j < 4; j++) rk[j] = ks[tx * 4 + j][d];
        #pragma unroll
        for (int i = 0; i < 4; i++)
            #pragma unroll
            for (int j = 0; j < 4; j++)
                acc[i][j] = fmaf(rq[i], rk[j], acc[i][j]);
    }

    // scale + rel bias + shift mask
    bool lastRow = (n >> 3) == 7;
    bool lastCol = (n & 7)  == 7;
    const float scale = 0.17677669529663689f;   // 1/sqrt(32)
    #pragma unroll
    for (int i = 0; i < 4; i++) {
        int p = ty * 4 + i;
        int pi = p >> 3, pj = p & 7;
        #pragma unroll
        for (int j = 0; j < 4; j++) {
            int q = tx * 4 + j;
            int qi = q >> 3, qj = q & 7;
            float v = acc[i][j] * scale + g_btab[h * 4096 + p * 64 + q];
            bool m = (lastRow && ((pi < 4) != (qi < 4))) ||
                     (lastCol && ((pj < 4) != (qj < 4)));
            sim[p][q] = m ? -1e30f : v;
        }
    }
    __syncthreads();

    // softmax: warp per 8 rows, lane handles cols {lane, lane+32}
    int wid = tid >> 5, lane = tid & 31;
    #pragma unroll
    for (int rr = 0; rr < 8; rr++) {
        int p = wid * 8 + rr;
        float a0 = sim[p][lane], a1 = sim[p][lane + 32];
        float m = fmaxf(a0, a1);
        #pragma unroll
        for (int o = 16; o; o >>= 1) m = fmaxf(m, __shfl_xor_sync(0xffffffffu, m, o));
        float e0 = __expf(a0 - m), e1 = __expf(a1 - m);
        float s = e0 + e1;
        #pragma unroll
        for (int o = 16; o; o >>= 1) s += __shfl_xor_sync(0xffffffffu, s, o);
        float inv = 1.0f / s;
        sim[p][lane] = e0 * inv;
        sim[p][lane + 32] = e1 * inv;
    }
    __syncthreads();

    // O = P @ V (64x32, each thread 4x2)
    float acc2[4][2];
    #pragma unroll
    for (int i = 0; i < 4; i++) { acc2[i][0] = 0.0f; acc2[i][1] = 0.0f; }
    #pragma unroll
    for (int kk = 0; kk < 64; kk++) {
        float rp[4], rv[2];
        #pragma unroll
        for (int i = 0; i < 4; i++) rp[i] = sim[ty * 4 + i][kk];
        rv[0] = vs[kk][tx * 2];
        rv[1] = vs[kk][tx * 2 + 1];
        #pragma unroll
        for (int i = 0; i < 4; i++) {
            acc2[i][0] = fmaf(rp[i], rv[0], acc2[i][0]);
            acc2[i][1] = fmaf(rp[i], rv[1], acc2[i][1]);
        }
    }
    #pragma unroll
    for (int i = 0; i < 4; i++) {
        int p = ty * 4 + i;
        #pragma unroll
        for (int j = 0; j < 2; j++) {
            g_attn[(rowbase + p) * kC + h * kHD + tx * 2 + j] = acc2[i][j];
        }
    }
}

// ---------------- launch ----------------
extern "C" void kernel_launch(void* const* d_in, const int* in_sizes, int n_in,
                              void* d_out, int out_size) {
    const float* x      = (const float*)d_in[0];
    const float* g1     = (const float*)d_in[1];
    const float* b1     = (const float*)d_in[2];
    const float* w_qkv  = (const float*)d_in[3];
    const float* b_qkv  = (const float*)d_in[4];
    const float* relp   = (const float*)d_in[5];
    const float* w_proj = (const float*)d_in[6];
    const float* b_proj = (const float*)d_in[7];
    const float* g2     = (const float*)d_in[8];
    const float* b2     = (const float*)d_in[9];
    const float* w_mlp1 = (const float*)d_in[10];
    const float* b_mlp1 = (const float*)d_in[11];
    const float* w_mlp2 = (const float*)d_in[12];
    const float* b_mlp2 = (const float*)d_in[13];
    float* out = (float*)d_out;

    float *hwin, *qkvb, *attnb, *x1, *h2n, *mid;
    cudaGetSymbolAddress((void**)&hwin,  g_hwin);
    cudaGetSymbolAddress((void**)&qkvb,  g_qkv);
    cudaGetSymbolAddress((void**)&attnb, g_attn);
    cudaGetSymbolAddress((void**)&x1,    g_x1);
    cudaGetSymbolAddress((void**)&h2n,   g_h2n);
    cudaGetSymbolAddress((void**)&mid,   g_mid);

    // 1. relative-position bias table
    btab_kernel<<<(kNH * kPP * kPP + 255) / 256, 256>>>(relp);
    // 2. LN1 + roll + window partition
    ln1_kernel<<<kTOK, kC>>>(x, g1, b1);
    // 3. QKV GEMM: [65536,192] @ [192,576]
    sgemm_kernel<0><<<dim3(576 / 64, kTOK / 128), 256>>>(
        hwin, w_qkv, b_qkv, nullptr, qkvb, kTOK, 576, kC);
    // 4. windowed attention
    attn_kernel<<<kB * kNW * kNH, 256>>>();
    // 5. proj GEMM + window-reverse + roll-back + residual
    sgemm_kernel<2><<<dim3(kC / 64, kTOK / 128), 256>>>(
        attnb, w_proj, b_proj, x, x1, kTOK, kC, kC);
    // 6. LN2
    ln2_kernel<<<kTOK, kC>>>(g2, b2);
    // 7. MLP1 + GELU
    sgemm_kernel<1><<<dim3(768 / 64, kTOK / 128), 256>>>(
        h2n, w_mlp1, b_mlp1, nullptr, mid, kTOK, 768, kC);
    // 8. MLP2 + residual -> out
    sgemm_kernel<3><<<dim3(kC / 64, kTOK / 128), 256>>>(
        mid, w_mlp2, b_mlp2, x1, out, kTOK, kC, 768);
}

// round 6
// speedup vs baseline: 1.9482x; 1.9482x over previous
#include <cuda_runtime.h>
#include <math.h>
#include <stdint.h>

// ---------------- problem constants ----------------
#define kB    16
#define kH    64
#define kW    64
#define kC    192
#define kHD   32
#define kNH   6
#define kP    8
#define kSH   4            // SHIFT
#define kNW   64           // (H/P)*(W/P)
#define kPP   64           // P*P
#define kTOK  (kB*kH*kW)   // 65536

// ---------------- device scratch (no allocation allowed) ----------------
__device__ float g_hwin[(size_t)kTOK * kC];        //  50 MB  LN1+windowed
__device__ float g_qkv [(size_t)kTOK * 3 * kC];    // 151 MB
__device__ float g_attn[(size_t)kTOK * kC];        //  50 MB
__device__ float g_x1  [(size_t)kTOK * kC];        //  50 MB  after attn residual
__device__ float g_h2n [(size_t)kTOK * kC];        //  50 MB  LN2 out
__device__ float g_mid [(size_t)kTOK * 4 * kC];    // 201 MB  MLP hidden
__device__ float g_btab[kNH * kPP * kPP];          // rel-pos bias table

// ---------------- small PTX helpers (sm_80-level only; no arch-'a' features) -----
__device__ __forceinline__ uint32_t f2tf(float x) {
    uint32_t u;
    asm("cvt.rna.tf32.f32 %0, %1;" : "=r"(u) : "f"(x));
    return u;
}

__device__ __forceinline__ void mma_tf32(float* d,
                                         uint32_t a0, uint32_t a1, uint32_t a2, uint32_t a3,
                                         uint32_t b0, uint32_t b1) {
    asm volatile(
        "mma.sync.aligned.m16n8k8.row.col.f32.tf32.tf32.f32 "
        "{%0,%1,%2,%3}, {%4,%5,%6,%7}, {%8,%9}, {%0,%1,%2,%3};"
        : "+f"(d[0]), "+f"(d[1]), "+f"(d[2]), "+f"(d[3])
        : "r"(a0), "r"(a1), "r"(a2), "r"(a3), "r"(b0), "r"(b1));
}

// ---------------- relative position bias table ----------------
__global__ void btab_kernel(const float* __restrict__ rel) {
    int idx = blockIdx.x * 256 + threadIdx.x;
    if (idx >= kNH * kPP * kPP) return;
    int h = idx >> 12;
    int r = idx & 4095;
    int p = r >> 6, q = r & 63;
    int dy = (p >> 3) - (q >> 3) + (kP - 1);
    int dx = (p & 7)  - (q & 7)  + (kP - 1);
    g_btab[idx] = rel[h * (2*kP-1)*(2*kP-1) + dy * (2*kP-1) + dx];
}

// ---------------- LayerNorm kernels ----------------
__global__ void ln1_kernel(const float* __restrict__ x,
                           const float* __restrict__ g,
                           const float* __restrict__ bt) {
    int t = blockIdx.x;
    int c = threadIdx.x;
    int b = t >> 12;
    int ij = t & 4095;
    int i = ij >> 6, j = ij & 63;
    int si = (i + kSH) & 63, sj = (j + kSH) & 63;
    float v = x[((size_t)(((b << 6) + si) << 6) + sj) * kC + c];

    __shared__ float red1[6], red2[6];
    int wid = c >> 5, lane = c & 31;
    float s = v;
    #pragma unroll
    for (int o = 16; o; o >>= 1) s += __shfl_xor_sync(0xffffffffu, s, o);
    if (lane == 0) red1[wid] = s;
    __syncthreads();
    float mean = (red1[0]+red1[1]+red1[2]+red1[3]+red1[4]+red1[5]) * (1.0f/kC);
    float d = v - mean;
    float q = d * d;
    #pragma unroll
    for (int o = 16; o; o >>= 1) q += __shfl_xor_sync(0xffffffffu, q, o);
    if (lane == 0) red2[wid] = q;
    __syncthreads();
    float var = (red2[0]+red2[1]+red2[2]+red2[3]+red2[4]+red2[5]) * (1.0f/kC);
    float out = d * rsqrtf(var + 1e-5f) * g[c] + bt[c];

    int wi = i >> 3, pi = i & 7, wj = j >> 3, pj = j & 7;
    int n  = (wi << 3) + wj;
    int p  = (pi << 3) + pj;
    size_t row = (size_t)((b << 6) + n) * 64 + p;
    g_hwin[row * kC + c] = out;
}

__global__ void ln2_kernel(const float* __restrict__ g,
                           const float* __restrict__ bt) {
    int t = blockIdx.x;
    int c = threadIdx.x;
    float v = g_x1[(size_t)t * kC + c];

    __shared__ float red1[6], red2[6];
    int wid = c >> 5, lane = c & 31;
    float s = v;
    #pragma unroll
    for (int o = 16; o; o >>= 1) s += __shfl_xor_sync(0xffffffffu, s, o);
    if (lane == 0) red1[wid] = s;
    __syncthreads();
    float mean = (red1[0]+red1[1]+red1[2]+red1[3]+red1[4]+red1[5]) * (1.0f/kC);
    float d = v - mean;
    float q = d * d;
    #pragma unroll
    for (int o = 16; o; o >>= 1) q += __shfl_xor_sync(0xffffffffu, q, o);
    if (lane == 0) red2[wid] = q;
    __syncthreads();
    float var = (red2[0]+red2[1]+red2[2]+red2[3]+red2[4]+red2[5]) * (1.0f/kC);
    g_h2n[(size_t)t * kC + c] = d * rsqrtf(var + 1e-5f) * g[c] + bt[c];
}

// ---------------- window-reverse + roll-back row mapping ----------------
__device__ __forceinline__ int map_row(int r) {
    int b   = r >> 12;
    int rem = r & 4095;
    int n = rem >> 6, p = rem & 63;
    int wi = n >> 3, wj = n & 7;
    int pi = p >> 3, pj = p & 7;
    int i = (wi * kP + pi + kSH) & 63;
    int j = (wj * kP + pj + kSH) & 63;
    return (((b << 6) + i) << 6) + j;
}

// ================= tf32 mma.sync GEMM =================
// C[M,N] = A[M,K] @ W[K,N] + bias.  BM=128, BN=64, BK=16, 4 warps, warp tile 32x64.
// EPI: 0 plain, 1 GELU, 2 proj(scatter+residual), 3 residual.
template<int EPI>
__global__ void __launch_bounds__(128, 3) mma_gemm(
    const float* __restrict__ A, const float* __restrict__ W,
    const float* __restrict__ bias, const float* __restrict__ R,
    float* __restrict__ Co, int M, int N, int K)
{
    // padded layouts => conflict-free fragment LDS
    __shared__ uint32_t As[2][128][20];   // [buf][m][k] stride 20
    __shared__ uint32_t Bs[2][16][72];    // [buf][k][n] stride 72

    int tid = threadIdx.x;
    int w = tid >> 5, l = tid & 31;
    int bm = blockIdx.y << 7;
    int bn = blockIdx.x << 6;

    float acc[2][8][4];
    #pragma unroll
    for (int mt = 0; mt < 2; mt++)
        #pragma unroll
        for (int nt = 0; nt < 8; nt++)
            #pragma unroll
            for (int e = 0; e < 4; e++) acc[mt][nt][e] = 0.0f;

    // A staging mapping: thread covers rows r = (tid>>2) + 32*j (j=0..3), k-seg q = tid&3
    int a_r0 = tid >> 2;            // 0..31
    int a_q  = tid & 3;             // 0..3 (float4 within 16-k chunk)
    // B staging: thread covers (k = tid>>4 and +8, n4 = (tid&15)*4)
    int b_k  = tid >> 4;            // 0..7
    int b_n4 = (tid & 15) << 2;     // 0..60

    const float* Bp = W + (size_t)b_k * N + bn + b_n4;
    int NC = K >> 4;

    float4 av[4];
    float4 bv[2];

    // ---- prologue: load chunk 0 ----
    #pragma unroll
    for (int j = 0; j < 4; j++)
        av[j] = *(const float4*)(A + (size_t)(bm + a_r0 + 32*j) * K + a_q * 4);
    bv[0] = *(const float4*)(Bp);
    bv[1] = *(const float4*)(Bp + (size_t)8 * N);

    // ---- STS chunk 0 into buf 0 ----
    #pragma unroll
    for (int j = 0; j < 4; j++) {
        uint4 u = make_uint4(f2tf(av[j].x), f2tf(av[j].y), f2tf(av[j].z), f2tf(av[j].w));
        *(uint4*)&As[0][a_r0 + 32*j][a_q * 4] = u;
    }
    {
        uint4 u0 = make_uint4(f2tf(bv[0].x), f2tf(bv[0].y), f2tf(bv[0].z), f2tf(bv[0].w));
        uint4 u1 = make_uint4(f2tf(bv[1].x), f2tf(bv[1].y), f2tf(bv[1].z), f2tf(bv[1].w));
        *(uint4*)&Bs[0][b_k][b_n4]     = u0;
        *(uint4*)&Bs[0][b_k + 8][b_n4] = u1;
    }
    __syncthreads();

    for (int c = 0; c < NC; c++) {
        // prefetch next chunk while computing this one
        if (c + 1 < NC) {
            int koff = (c + 1) * 16;
            #pragma unroll
            for (int j = 0; j < 4; j++)
                av[j] = *(const float4*)(A + (size_t)(bm + a_r0 + 32*j) * K + koff + a_q * 4);
            const float* bp = Bp + (size_t)koff * N;
            bv[0] = *(const float4*)(bp);
            bv[1] = *(const float4*)(bp + (size_t)8 * N);
        }
        int buf = c & 1;
        #pragma unroll
        for (int s = 0; s < 2; s++) {
            int kk = s * 8 + (l & 3);
            uint32_t af[2][4];
            #pragma unroll
            for (int mt = 0; mt < 2; mt++) {
                int m = w * 32 + mt * 16 + (l >> 2);
                af[mt][0] = As[buf][m][kk];
                af[mt][1] = As[buf][m + 8][kk];
                af[mt][2] = As[buf][m][kk + 4];
                af[mt][3] = As[buf][m + 8][kk + 4];
            }
            uint32_t bf[8][2];
            #pragma unroll
            for (int nt = 0; nt < 8; nt++) {
                int n = nt * 8 + (l >> 2);
                bf[nt][0] = Bs[buf][kk][n];
                bf[nt][1] = Bs[buf][kk + 4][n];
            }
            #pragma unroll
            for (int mt = 0; mt < 2; mt++)
                #pragma unroll
                for (int nt = 0; nt < 8; nt++)
                    mma_tf32(acc[mt][nt], af[mt][0], af[mt][1], af[mt][2], af[mt][3],
                             bf[nt][0], bf[nt][1]);
        }
        if (c + 1 < NC) {
            int nb = (c + 1) & 1;
            #pragma unroll
            for (int j = 0; j < 4; j++) {
                uint4 u = make_uint4(f2tf(av[j].x), f2tf(av[j].y), f2tf(av[j].z), f2tf(av[j].w));
                *(uint4*)&As[nb][a_r0 + 32*j][a_q * 4] = u;
            }
            uint4 u0 = make_uint4(f2tf(bv[0].x), f2tf(bv[0].y), f2tf(bv[0].z), f2tf(bv[0].w));
            uint4 u1 = make_uint4(f2tf(bv[1].x), f2tf(bv[1].y), f2tf(bv[1].z), f2tf(bv[1].w));
            *(uint4*)&Bs[nb][b_k][b_n4]     = u0;
            *(uint4*)&Bs[nb][b_k + 8][b_n4] = u1;
        }
        __syncthreads();
    }

    // ---- epilogue ----
    #pragma unroll
    for (int mt = 0; mt < 2; mt++) {
        int r0 = bm + w * 32 + mt * 16 + (l >> 2);
        int r1 = r0 + 8;
        int o0 = (EPI == 2) ? map_row(r0) : r0;
        int o1 = (EPI == 2) ? map_row(r1) : r1;
        #pragma unroll
        for (int nt = 0; nt < 8; nt++) {
            int col = bn + nt * 8 + ((l & 3) << 1);
            float2 bb = *(const float2*)(bias + col);
            float v0 = acc[mt][nt][0] + bb.x;
            float v1 = acc[mt][nt][1] + bb.y;
            float v2 = acc[mt][nt][2] + bb.x;
            float v3 = acc[mt][nt][3] + bb.y;
            if (EPI == 1) {
                v0 = 0.5f * v0 * (1.0f + erff(v0 * 0.70710678118654752f));
                v1 = 0.5f * v1 * (1.0f + erff(v1 * 0.70710678118654752f));
                v2 = 0.5f * v2 * (1.0f + erff(v2 * 0.70710678118654752f));
                v3 = 0.5f * v3 * (1.0f + erff(v3 * 0.70710678118654752f));
            }
            if (EPI == 2 || EPI == 3) {
                float2 ra = *(const float2*)(R + (size_t)o0 * N + col);
                float2 rb = *(const float2*)(R + (size_t)o1 * N + col);
                v0 += ra.x; v1 += ra.y; v2 += rb.x; v3 += rb.y;
            }
            *(float2*)(Co + (size_t)o0 * N + col) = make_float2(v0, v1);
            *(float2*)(Co + (size_t)o1 * N + col) = make_float2(v2, v3);
        }
    }
}

// ---------------- windowed attention: one block per (b, window, head) ----------------
__global__ void __launch_bounds__(256) attn_kernel() {
    __shared__ float qs[64][33];
    __shared__ float ks[64][33];
    __shared__ float vs[64][33];
    __shared__ float sim[64][65];

    int tid = threadIdx.x;
    int h  = blockIdx.x % kNH;
    int bn = blockIdx.x / kNH;
    int n  = bn & 63;
    size_t rowbase = (size_t)bn * 64;

    #pragma unroll
    for (int it = 0; it < 2; it++) {
        int idx = tid + it * 256;
        int r = idx >> 3;
        int f = (idx & 7) << 2;
        const float* base = &g_qkv[(rowbase + r) * (3 * kC) + h * kHD + f];
        float4 qv = *(const float4*)(base);
        float4 kv = *(const float4*)(base + kC);
        float4 vv = *(const float4*)(base + 2 * kC);
        qs[r][f] = qv.x; qs[r][f+1] = qv.y; qs[r][f+2] = qv.z; qs[r][f+3] = qv.w;
        ks[r][f] = kv.x; ks[r][f+1] = kv.y; ks[r][f+2] = kv.z; ks[r][f+3] = kv.w;
        vs[r][f] = vv.x; vs[r][f+1] = vv.y; vs[r][f+2] = vv.z; vs[r][f+3] = vv.w;
    }
    __syncthreads();

    int ty = tid >> 4, tx = tid & 15;

    float acc[4][4];
    #pragma unroll
    for (int i = 0; i < 4; i++)
        #pragma unroll
        for (int j = 0; j < 4; j++) acc[i][j] = 0.0f;
    #pragma unroll
    for (int d = 0; d < 32; d++) {
        float rq[4], rk[4];
        #pragma unroll
        for (int i = 0; i < 4; i++) rq[i] = qs[ty * 4 + i][d];
        #pragma unroll
        for (int j = 0; j < 4; j++) rk[j] = ks[tx * 4 + j][d];
        #pragma unroll
        for (int i = 0; i < 4; i++)
            #pragma unroll
            for (int j = 0; j < 4; j++)
                acc[i][j] = fmaf(rq[i], rk[j], acc[i][j]);
    }

    bool lastRow = (n >> 3) == 7;
    bool lastCol = (n & 7)  == 7;
    const float scale = 0.17677669529663689f;
    #pragma unroll
    for (int i = 0; i < 4; i++) {
        int p = ty * 4 + i;
        int pi = p >> 3, pj = p & 7;
        #pragma unroll
        for (int j = 0; j < 4; j++) {
            int q = tx * 4 + j;
            int qi = q >> 3, qj = q & 7;
            float v = acc[i][j] * scale + g_btab[h * 4096 + p * 64 + q];
            bool m = (lastRow && ((pi < 4) != (qi < 4))) ||
                     (lastCol && ((pj < 4) != (qj < 4)));
            sim[p][q] = m ? -1e30f : v;
        }
    }
    __syncthreads();

    int wid = tid >> 5, lane = tid & 31;
    #pragma unroll
    for (int rr = 0; rr < 8; rr++) {
        int p = wid * 8 + rr;
        float a0 = sim[p][lane], a1 = sim[p][lane + 32];
        float m = fmaxf(a0, a1);
        #pragma unroll
        for (int o = 16; o; o >>= 1) m = fmaxf(m, __shfl_xor_sync(0xffffffffu, m, o));
        float e0 = __expf(a0 - m), e1 = __expf(a1 - m);
        float s = e0 + e1;
        #pragma unroll
        for (int o = 16; o; o >>= 1) s += __shfl_xor_sync(0xffffffffu, s, o);
        float inv = 1.0f / s;
        sim[p][lane] = e0 * inv;
        sim[p][lane + 32] = e1 * inv;
    }
    __syncthreads();

    float acc2[4][2];
    #pragma unroll
    for (int i = 0; i < 4; i++) { acc2[i][0] = 0.0f; acc2[i][1] = 0.0f; }
    #pragma unroll
    for (int kk = 0; kk < 64; kk++) {
        float rp[4], rv[2];
        #pragma unroll
        for (int i = 0; i < 4; i++) rp[i] = sim[ty * 4 + i][kk];
        rv[0] = vs[kk][tx * 2];
        rv[1] = vs[kk][tx * 2 + 1];
        #pragma unroll
        for (int i = 0; i < 4; i++) {
            acc2[i][0] = fmaf(rp[i], rv[0], acc2[i][0]);
            acc2[i][1] = fmaf(rp[i], rv[1], acc2[i][1]);
        }
    }
    #pragma unroll
    for (int i = 0; i < 4; i++) {
        int p = ty * 4 + i;
        #pragma unroll
        for (int j = 0; j < 2; j++) {
            g_attn[(rowbase + p) * kC + h * kHD + tx * 2 + j] = acc2[i][j];
        }
    }
}

// ---------------- launch ----------------
extern "C" void kernel_launch(void* const* d_in, const int* in_sizes, int n_in,
                              void* d_out, int out_size) {
    const float* x      = (const float*)d_in[0];
    const float* g1     = (const float*)d_in[1];
    const float* b1     = (const float*)d_in[2];
    const float* w_qkv  = (const float*)d_in[3];
    const float* b_qkv  = (const float*)d_in[4];
    const float* relp   = (const float*)d_in[5];
    const float* w_proj = (const float*)d_in[6];
    const float* b_proj = (const float*)d_in[7];
    const float* g2     = (const float*)d_in[8];
    const float* b2     = (const float*)d_in[9];
    const float* w_mlp1 = (const float*)d_in[10];
    const float* b_mlp1 = (const float*)d_in[11];
    const float* w_mlp2 = (const float*)d_in[12];
    const float* b_mlp2 = (const float*)d_in[13];
    float* out = (float*)d_out;

    float *hwin, *qkvb, *attnb, *x1, *h2n, *mid;
    cudaGetSymbolAddress((void**)&hwin,  g_hwin);
    cudaGetSymbolAddress((void**)&qkvb,  g_qkv);
    cudaGetSymbolAddress((void**)&attnb, g_attn);
    cudaGetSymbolAddress((void**)&x1,    g_x1);
    cudaGetSymbolAddress((void**)&h2n,   g_h2n);
    cudaGetSymbolAddress((void**)&mid,   g_mid);

    // 1. relative-position bias table
    btab_kernel<<<(kNH * kPP * kPP + 255) / 256, 256>>>(relp);
    // 2. LN1 + roll + window partition
    ln1_kernel<<<kTOK, kC>>>(x, g1, b1);
    // 3. QKV GEMM: [65536,192] @ [192,576]
    mma_gemm<0><<<dim3(576 / 64, kTOK / 128), 128>>>(
        hwin, w_qkv, b_qkv, nullptr, qkvb, kTOK, 576, kC);
    // 4. windowed attention
    attn_kernel<<<kB * kNW * kNH, 256>>>();
    // 5. proj GEMM + window-reverse + roll-back + residual
    mma_gemm<2><<<dim3(kC / 64, kTOK / 128), 128>>>(
        attnb, w_proj, b_proj, x, x1, kTOK, kC, kC);
    // 6. LN2
    ln2_kernel<<<kTOK, kC>>>(g2, b2);
    // 7. MLP1 + GELU
    mma_gemm<1><<<dim3(768 / 64, kTOK / 128), 128>>>(
        h2n, w_mlp1, b_mlp1, nullptr, mid, kTOK, 768, kC);
    // 8. MLP2 + residual -> out
    mma_gemm<3><<<dim3(kC / 64, kTOK / 128), 128>>>(
        mid, w_mlp2, b_mlp2, x1, out, kTOK, kC, 768);
}

// round 7
// speedup vs baseline: 2.1557x; 1.1065x over previous
#include <cuda_runtime.h>
#include <math.h>
#include <stdint.h>

// ---------------- problem constants ----------------
#define kB    16
#define kH    64
#define kW    64
#define kC    192
#define kHD   32
#define kNH   6
#define kP    8
#define kSH   4            // SHIFT
#define kNW   64           // (H/P)*(W/P)
#define kPP   64           // P*P
#define kTOK  (kB*kH*kW)   // 65536

// ---------------- device scratch (no allocation allowed) ----------------
__device__ float g_hwin[(size_t)kTOK * kC];
__device__ float g_qkv [(size_t)kTOK * 3 * kC];
__device__ float g_attn[(size_t)kTOK * kC];
__device__ float g_x1  [(size_t)kTOK * kC];
__device__ float g_h2n [(size_t)kTOK * kC];
__device__ float g_mid [(size_t)kTOK * 4 * kC];
__device__ float g_btab[kNH * kPP * kPP];

// ---------------- PTX helpers (sm_80-level only) ----------------
__device__ __forceinline__ void mma_tf32(float* d,
                                         uint32_t a0, uint32_t a1, uint32_t a2, uint32_t a3,
                                         uint32_t b0, uint32_t b1) {
    asm volatile(
        "mma.sync.aligned.m16n8k8.row.col.f32.tf32.tf32.f32 "
        "{%0,%1,%2,%3}, {%4,%5,%6,%7}, {%8,%9}, {%0,%1,%2,%3};"
        : "+f"(d[0]), "+f"(d[1]), "+f"(d[2]), "+f"(d[3])
        : "r"(a0), "r"(a1), "r"(a2), "r"(a3), "r"(b0), "r"(b1));
}
__device__ __forceinline__ uint32_t s2u(const void* p) {
    return (uint32_t)__cvta_generic_to_shared(p);
}
__device__ __forceinline__ void cpa16(uint32_t dst, const void* src) {
    asm volatile("cp.async.cg.shared.global [%0], [%1], 16;" :: "r"(dst), "l"(src));
}
__device__ __forceinline__ void cpa_commit() {
    asm volatile("cp.async.commit_group;" ::: "memory");
}
template<int N> __device__ __forceinline__ void cpa_wait() {
    asm volatile("cp.async.wait_group %0;" :: "n"(N) : "memory");
}

// ---------------- relative position bias table ----------------
__global__ void btab_kernel(const float* __restrict__ rel) {
    int idx = blockIdx.x * 256 + threadIdx.x;
    if (idx >= kNH * kPP * kPP) return;
    int h = idx >> 12;
    int r = idx & 4095;
    int p = r >> 6, q = r & 63;
    int dy = (p >> 3) - (q >> 3) + (kP - 1);
    int dx = (p & 7)  - (q & 7)  + (kP - 1);
    g_btab[idx] = rel[h * (2*kP-1)*(2*kP-1) + dy * (2*kP-1) + dx];
}

// ---------------- LayerNorm kernels ----------------
__global__ void ln1_kernel(const float* __restrict__ x,
                           const float* __restrict__ g,
                           const float* __restrict__ bt) {
    int t = blockIdx.x;
    int c = threadIdx.x;
    int b = t >> 12;
    int ij = t & 4095;
    int i = ij >> 6, j = ij & 63;
    int si = (i + kSH) & 63, sj = (j + kSH) & 63;
    float v = x[((size_t)(((b << 6) + si) << 6) + sj) * kC + c];

    __shared__ float red1[6], red2[6];
    int wid = c >> 5, lane = c & 31;
    float s = v;
    #pragma unroll
    for (int o = 16; o; o >>= 1) s += __shfl_xor_sync(0xffffffffu, s, o);
    if (lane == 0) red1[wid] = s;
    __syncthreads();
    float mean = (red1[0]+red1[1]+red1[2]+red1[3]+red1[4]+red1[5]) * (1.0f/kC);
    float d = v - mean;
    float q = d * d;
    #pragma unroll
    for (int o = 16; o; o >>= 1) q += __shfl_xor_sync(0xffffffffu, q, o);
    if (lane == 0) red2[wid] = q;
    __syncthreads();
    float var = (red2[0]+red2[1]+red2[2]+red2[3]+red2[4]+red2[5]) * (1.0f/kC);
    float out = d * rsqrtf(var + 1e-5f) * g[c] + bt[c];

    int wi = i >> 3, pi = i & 7, wj = j >> 3, pj = j & 7;
    int n  = (wi << 3) + wj;
    int p  = (pi << 3) + pj;
    size_t row = (size_t)((b << 6) + n) * 64 + p;
    g_hwin[row * kC + c] = out;
}

__global__ void ln2_kernel(const float* __restrict__ g,
                           const float* __restrict__ bt) {
    int t = blockIdx.x;
    int c = threadIdx.x;
    float v = g_x1[(size_t)t * kC + c];

    __shared__ float red1[6], red2[6];
    int wid = c >> 5, lane = c & 31;
    float s = v;
    #pragma unroll
    for (int o = 16; o; o >>= 1) s += __shfl_xor_sync(0xffffffffu, s, o);
    if (lane == 0) red1[wid] = s;
    __syncthreads();
    float mean = (red1[0]+red1[1]+red1[2]+red1[3]+red1[4]+red1[5]) * (1.0f/kC);
    float d = v - mean;
    float q = d * d;
    #pragma unroll
    for (int o = 16; o; o >>= 1) q += __shfl_xor_sync(0xffffffffu, q, o);
    if (lane == 0) red2[wid] = q;
    __syncthreads();
    float var = (red2[0]+red2[1]+red2[2]+red2[3]+red2[4]+red2[5]) * (1.0f/kC);
    g_h2n[(size_t)t * kC + c] = d * rsqrtf(var + 1e-5f) * g[c] + bt[c];
}

// ---------------- window-reverse + roll-back row mapping ----------------
__device__ __forceinline__ int map_row(int r) {
    int b   = r >> 12;
    int rem = r & 4095;
    int n = rem >> 6, p = rem & 63;
    int wi = n >> 3, wj = n & 7;
    int pi = p >> 3, pj = p & 7;
    int i = (wi * kP + pi + kSH) & 63;
    int j = (wj * kP + pj + kSH) & 63;
    return (((b << 6) + i) << 6) + j;
}

// ================= tf32 mma.sync GEMM, cp.async 3-stage =================
// C[M,N] = A[M,K] @ W[K,N] + bias.  BM=128, BN=64, BK=16, 4 warps, warp tile 32x64.
// EPI: 0 plain, 1 GELU, 2 proj(scatter+residual), 3 residual.
#define ASTR 20          // As row stride (floats)
#define BSTR 72          // Bs row stride (floats)
#define A_STAGE (128*ASTR)    // 2560 floats
#define B_STAGE (16*BSTR)     // 1152 floats
#define GEMM_SMEM ((3*A_STAGE + 3*B_STAGE) * 4)   // 44544 bytes

template<int EPI>
__global__ void __launch_bounds__(128, 4) mma_gemm(
    const float* __restrict__ A, const float* __restrict__ W,
    const float* __restrict__ bias, const float* __restrict__ R,
    float* __restrict__ Co, int M, int N, int K)
{
    extern __shared__ float sm[];
    float* AsB = sm;                 // 3 stages of A
    float* BsB = sm + 3 * A_STAGE;   // 3 stages of B

    int tid = threadIdx.x;
    int w = tid >> 5, l = tid & 31;
    int bm = blockIdx.y << 7;
    int bn = blockIdx.x << 6;

    float acc[2][8][4];
    #pragma unroll
    for (int mt = 0; mt < 2; mt++)
        #pragma unroll
        for (int nt = 0; nt < 8; nt++)
            #pragma unroll
            for (int e = 0; e < 4; e++) acc[mt][nt][e] = 0.0f;

    int a_r0 = tid >> 2;            // 0..31
    int a_q  = tid & 3;             // float4 seg within 16-k chunk
    int b_k  = tid >> 4;            // 0..7
    int b_n4 = (tid & 15) << 2;     // 0..60

    int NC = K >> 4;

    // issue one chunk's cp.asyncs into stage buffer
    auto issue = [&](int c, int buf) {
        float* As = AsB + buf * A_STAGE;
        float* Bs = BsB + buf * B_STAGE;
        int koff = c * 16;
        #pragma unroll
        for (int j = 0; j < 4; j++)
            cpa16(s2u(&As[(a_r0 + 32*j) * ASTR + a_q * 4]),
                  A + (size_t)(bm + a_r0 + 32*j) * K + koff + a_q * 4);
        cpa16(s2u(&Bs[b_k * BSTR + b_n4]),
              W + (size_t)(koff + b_k) * N + bn + b_n4);
        cpa16(s2u(&Bs[(b_k + 8) * BSTR + b_n4]),
              W + (size_t)(koff + b_k + 8) * N + bn + b_n4);
        cpa_commit();
    };

    issue(0, 0);
    issue(1, 1);

    for (int c = 0; c < NC; c++) {
        cpa_wait<1>();
        __syncthreads();
        if (c + 2 < NC) issue(c + 2, (c + 2) % 3);

        int buf = c % 3;
        const float* As = AsB + buf * A_STAGE;
        const float* Bs = BsB + buf * B_STAGE;
        #pragma unroll
        for (int s = 0; s < 2; s++) {
            int kk = s * 8 + (l & 3);
            uint32_t af[2][4];
            #pragma unroll
            for (int mt = 0; mt < 2; mt++) {
                int m = w * 32 + mt * 16 + (l >> 2);
                af[mt][0] = __float_as_uint(As[m * ASTR + kk]);
                af[mt][1] = __float_as_uint(As[(m + 8) * ASTR + kk]);
                af[mt][2] = __float_as_uint(As[m * ASTR + kk + 4]);
                af[mt][3] = __float_as_uint(As[(m + 8) * ASTR + kk + 4]);
            }
            uint32_t bf[8][2];
            #pragma unroll
            for (int nt = 0; nt < 8; nt++) {
                int n = nt * 8 + (l >> 2);
                bf[nt][0] = __float_as_uint(Bs[kk * BSTR + n]);
                bf[nt][1] = __float_as_uint(Bs[(kk + 4) * BSTR + n]);
            }
            #pragma unroll
            for (int mt = 0; mt < 2; mt++)
                #pragma unroll
                for (int nt = 0; nt < 8; nt++)
                    mma_tf32(acc[mt][nt], af[mt][0], af[mt][1], af[mt][2], af[mt][3],
                             bf[nt][0], bf[nt][1]);
        }
        __syncthreads();
    }

    // ---- epilogue ----
    #pragma unroll
    for (int mt = 0; mt < 2; mt++) {
        int r0 = bm + w * 32 + mt * 16 + (l >> 2);
        int r1 = r0 + 8;
        int o0 = (EPI == 2) ? map_row(r0) : r0;
        int o1 = (EPI == 2) ? map_row(r1) : r1;
        #pragma unroll
        for (int nt = 0; nt < 8; nt++) {
            int col = bn + nt * 8 + ((l & 3) << 1);
            float2 bb = *(const float2*)(bias + col);
            float v0 = acc[mt][nt][0] + bb.x;
            float v1 = acc[mt][nt][1] + bb.y;
            float v2 = acc[mt][nt][2] + bb.x;
            float v3 = acc[mt][nt][3] + bb.y;
            if (EPI == 1) {
                v0 = 0.5f * v0 * (1.0f + erff(v0 * 0.70710678118654752f));
                v1 = 0.5f * v1 * (1.0f + erff(v1 * 0.70710678118654752f));
                v2 = 0.5f * v2 * (1.0f + erff(v2 * 0.70710678118654752f));
                v3 = 0.5f * v3 * (1.0f + erff(v3 * 0.70710678118654752f));
            }
            if (EPI == 2 || EPI == 3) {
                float2 ra = *(const float2*)(R + (size_t)o0 * N + col);
                float2 rb = *(const float2*)(R + (size_t)o1 * N + col);
                v0 += ra.x; v1 += ra.y; v2 += rb.x; v3 += rb.y;
            }
            *(float2*)(Co + (size_t)o0 * N + col) = make_float2(v0, v1);
            *(float2*)(Co + (size_t)o1 * N + col) = make_float2(v2, v3);
        }
    }
}

// ---------------- windowed attention (smem-layout optimized) ----------------
// qt/kt: d-major [32][68]; vs: k-major [64][36]; sim: [64][68]
__global__ void __launch_bounds__(256) attn_kernel() {
    __shared__ float qt[32][68];
    __shared__ float kt[32][68];
    __shared__ float vs[64][36];
    __shared__ float sim[64][68];

    int tid = threadIdx.x;
    int h  = blockIdx.x % kNH;
    int bn = blockIdx.x / kNH;
    int n  = bn & 63;
    size_t rowbase = (size_t)bn * 64;

    // load Q,K (transposed to d-major) and V (k-major)
    #pragma unroll
    for (int it = 0; it < 2; it++) {
        int idx = tid + it * 256;          // 0..511
        int r = idx >> 3;                  // token in window
        int f = (idx & 7) << 2;            // d-offset
        const float* base = &g_qkv[(rowbase + r) * (3 * kC) + h * kHD + f];
        float4 qv = *(const float4*)(base);
        float4 kv = *(const float4*)(base + kC);
        float4 vv = *(const float4*)(base + 2 * kC);
        qt[f + 0][r] = qv.x; qt[f + 1][r] = qv.y; qt[f + 2][r] = qv.z; qt[f + 3][r] = qv.w;
        kt[f + 0][r] = kv.x; kt[f + 1][r] = kv.y; kt[f + 2][r] = kv.z; kt[f + 3][r] = kv.w;
        *(float4*)&vs[r][f] = vv;
    }
    __syncthreads();

    int ty = tid >> 4, tx = tid & 15;

    // S = Q @ K^T  (64x64, each thread 4x4) — float4 fragment loads
    float acc[4][4];
    #pragma unroll
    for (int i = 0; i < 4; i++)
        #pragma unroll
        for (int j = 0; j < 4; j++) acc[i][j] = 0.0f;
    #pragma unroll
    for (int d = 0; d < 32; d++) {
        float4 rq = *(const float4*)&qt[d][ty * 4];
        float4 rk = *(const float4*)&kt[d][tx * 4];
        float aq[4] = {rq.x, rq.y, rq.z, rq.w};
        float ak[4] = {rk.x, rk.y, rk.z, rk.w};
        #pragma unroll
        for (int i = 0; i < 4; i++)
            #pragma unroll
            for (int j = 0; j < 4; j++)
                acc[i][j] = fmaf(aq[i], ak[j], acc[i][j]);
    }

    // scale + rel bias + shift mask, float4 stores to sim
    bool lastRow = (n >> 3) == 7;
    bool lastCol = (n & 7)  == 7;
    const float scale = 0.17677669529663689f;
    #pragma unroll
    for (int i = 0; i < 4; i++) {
        int p = ty * 4 + i;
        int pi = p >> 3, pj = p & 7;
        float4 bt4 = *(const float4*)&g_btab[h * 4096 + p * 64 + tx * 4];
        float bt[4] = {bt4.x, bt4.y, bt4.z, bt4.w};
        float o[4];
        #pragma unroll
        for (int j = 0; j < 4; j++) {
            int q = tx * 4 + j;
            int qi = q >> 3, qj = q & 7;
            float v = acc[i][j] * scale + bt[j];
            bool m = (lastRow && ((pi < 4) != (qi < 4))) ||
                     (lastCol && ((pj < 4) != (qj < 4)));
            o[j] = m ? -1e30f : v;
        }
        *(float4*)&sim[p][tx * 4] = make_float4(o[0], o[1], o[2], o[3]);
    }
    __syncthreads();

    // softmax: warp per 8 rows, lane handles cols {lane, lane+32}
    int wid = tid >> 5, lane = tid & 31;
    #pragma unroll
    for (int rr = 0; rr < 8; rr++) {
        int p = wid * 8 + rr;
        float a0 = sim[p][lane], a1 = sim[p][lane + 32];
        float m = fmaxf(a0, a1);
        #pragma unroll
        for (int o = 16; o; o >>= 1) m = fmaxf(m, __shfl_xor_sync(0xffffffffu, m, o));
        float e0 = __expf(a0 - m), e1 = __expf(a1 - m);
        float s = e0 + e1;
        #pragma unroll
        for (int o = 16; o; o >>= 1) s += __shfl_xor_sync(0xffffffffu, s, o);
        float inv = 1.0f / s;
        sim[p][lane] = e0 * inv;
        sim[p][lane + 32] = e1 * inv;
    }
    __syncthreads();

    // O = P @ V: thread owns one p-row (4 threads/row), 8 f-cols each
    int p  = tid >> 2;
    int f0 = (tid & 3) << 3;
    float a0 = 0, a1 = 0, a2 = 0, a3 = 0, a4 = 0, a5 = 0, a6 = 0, a7 = 0;
    #pragma unroll
    for (int kk = 0; kk < 64; kk++) {
        float wgt = sim[p][kk];
        float4 v0 = *(const float4*)&vs[kk][f0];
        float4 v1 = *(const float4*)&vs[kk][f0 + 4];
        a0 = fmaf(wgt, v0.x, a0); a1 = fmaf(wgt, v0.y, a1);
        a2 = fmaf(wgt, v0.z, a2); a3 = fmaf(wgt, v0.w, a3);
        a4 = fmaf(wgt, v1.x, a4); a5 = fmaf(wgt, v1.y, a5);
        a6 = fmaf(wgt, v1.z, a6); a7 = fmaf(wgt, v1.w, a7);
    }
    float* dst = &g_attn[(rowbase + p) * kC + h * kHD + f0];
    *(float4*)(dst)     = make_float4(a0, a1, a2, a3);
    *(float4*)(dst + 4) = make_float4(a4, a5, a6, a7);
}

// ---------------- launch ----------------
extern "C" void kernel_launch(void* const* d_in, const int* in_sizes, int n_in,
                              void* d_out, int out_size) {
    const float* x      = (const float*)d_in[0];
    const float* g1     = (const float*)d_in[1];
    const float* b1     = (const float*)d_in[2];
    const float* w_qkv  = (const float*)d_in[3];
    const float* b_qkv  = (const float*)d_in[4];
    const float* relp   = (const float*)d_in[5];
    const float* w_proj = (const float*)d_in[6];
    const float* b_proj = (const float*)d_in[7];
    const float* g2     = (const float*)d_in[8];
    const float* b2     = (const float*)d_in[9];
    const float* w_mlp1 = (const float*)d_in[10];
    const float* b_mlp1 = (const float*)d_in[11];
    const float* w_mlp2 = (const float*)d_in[12];
    const float* b_mlp2 = (const float*)d_in[13];
    float* out = (float*)d_out;

    float *hwin, *qkvb, *attnb, *x1, *h2n, *mid;
    cudaGetSymbolAddress((void**)&hwin,  g_hwin);
    cudaGetSymbolAddress((void**)&qkvb,  g_qkv);
    cudaGetSymbolAddress((void**)&attnb, g_attn);
    cudaGetSymbolAddress((void**)&x1,    g_x1);
    cudaGetSymbolAddress((void**)&h2n,   g_h2n);
    cudaGetSymbolAddress((void**)&mid,   g_mid);

    // 1. relative-position bias table
    btab_kernel<<<(kNH * kPP * kPP + 255) / 256, 256>>>(relp);
    // 2. LN1 + roll + window partition
    ln1_kernel<<<kTOK, kC>>>(x, g1, b1);
    // 3. QKV GEMM: [65536,192] @ [192,576]
    mma_gemm<0><<<dim3(576 / 64, kTOK / 128), 128, GEMM_SMEM>>>(
        hwin, w_qkv, b_qkv, nullptr, qkvb, kTOK, 576, kC);
    // 4. windowed attention
    attn_kernel<<<kB * kNW * kNH, 256>>>();
    // 5. proj GEMM + window-reverse + roll-back + residual
    mma_gemm<2><<<dim3(kC / 64, kTOK / 128), 128, GEMM_SMEM>>>(
        attnb, w_proj, b_proj, x, x1, kTOK, kC, kC);
    // 6. LN2
    ln2_kernel<<<kTOK, kC>>>(g2, b2);
    // 7. MLP1 + GELU
    mma_gemm<1><<<dim3(768 / 64, kTOK / 128), 128, GEMM_SMEM>>>(
        h2n, w_mlp1, b_mlp1, nullptr, mid, kTOK, 768, kC);
    // 8. MLP2 + residual -> out
    mma_gemm<3><<<dim3(kC / 64, kTOK / 128), 128, GEMM_SMEM>>>(
        mid, w_mlp2, b_mlp2, x1, out, kTOK, kC, 768);
}

// round 8
// speedup vs baseline: 2.4307x; 1.1276x over previous
#include <cuda_runtime.h>
#include <math.h>
#include <stdint.h>

// ---------------- problem constants ----------------
#define kB    16
#define kH    64
#define kW    64
#define kC    192
#define kHD   32
#define kNH   6
#define kP    8
#define kSH   4            // SHIFT
#define kNW   64           // (H/P)*(W/P)
#define kPP   64           // P*P
#define kTOK  (kB*kH*kW)   // 65536

// ---------------- device scratch (no allocation allowed) ----------------
__device__ float g_hwin[(size_t)kTOK * kC];
__device__ float g_qkv [(size_t)kTOK * 3 * kC];
__device__ float g_attn[(size_t)kTOK * kC];
__device__ float g_x1  [(size_t)kTOK * kC];
__device__ float g_h2n [(size_t)kTOK * kC];
__device__ float g_mid [(size_t)kTOK * 4 * kC];
__device__ float g_btab[kNH * kPP * kPP];

// ---------------- PTX helpers (sm_80-level only) ----------------
__device__ __forceinline__ void mma_tf32(float* d,
                                         uint32_t a0, uint32_t a1, uint32_t a2, uint32_t a3,
                                         uint32_t b0, uint32_t b1) {
    asm volatile(
        "mma.sync.aligned.m16n8k8.row.col.f32.tf32.tf32.f32 "
        "{%0,%1,%2,%3}, {%4,%5,%6,%7}, {%8,%9}, {%0,%1,%2,%3};"
        : "+f"(d[0]), "+f"(d[1]), "+f"(d[2]), "+f"(d[3])
        : "r"(a0), "r"(a1), "r"(a2), "r"(a3), "r"(b0), "r"(b1));
}
__device__ __forceinline__ uint32_t s2u(const void* p) {
    return (uint32_t)__cvta_generic_to_shared(p);
}
__device__ __forceinline__ void cpa16(uint32_t dst, const void* src) {
    asm volatile("cp.async.cg.shared.global [%0], [%1], 16;" :: "r"(dst), "l"(src));
}
__device__ __forceinline__ void cpa_commit() {
    asm volatile("cp.async.commit_group;" ::: "memory");
}
template<int N> __device__ __forceinline__ void cpa_wait() {
    asm volatile("cp.async.wait_group %0;" :: "n"(N) : "memory");
}

// ---------------- relative position bias table ----------------
__global__ void btab_kernel(const float* __restrict__ rel) {
    int idx = blockIdx.x * 256 + threadIdx.x;
    if (idx >= kNH * kPP * kPP) return;
    int h = idx >> 12;
    int r = idx & 4095;
    int p = r >> 6, q = r & 63;
    int dy = (p >> 3) - (q >> 3) + (kP - 1);
    int dx = (p & 7)  - (q & 7)  + (kP - 1);
    g_btab[idx] = rel[h * (2*kP-1)*(2*kP-1) + dy * (2*kP-1) + dx];
}

// ---------------- LayerNorm kernels ----------------
__global__ void ln1_kernel(const float* __restrict__ x,
                           const float* __restrict__ g,
                           const float* __restrict__ bt) {
    int t = blockIdx.x;
    int c = threadIdx.x;
    int b = t >> 12;
    int ij = t & 4095;
    int i = ij >> 6, j = ij & 63;
    int si = (i + kSH) & 63, sj = (j + kSH) & 63;
    float v = x[((size_t)(((b << 6) + si) << 6) + sj) * kC + c];

    __shared__ float red1[6], red2[6];
    int wid = c >> 5, lane = c & 31;
    float s = v;
    #pragma unroll
    for (int o = 16; o; o >>= 1) s += __shfl_xor_sync(0xffffffffu, s, o);
    if (lane == 0) red1[wid] = s;
    __syncthreads();
    float mean = (red1[0]+red1[1]+red1[2]+red1[3]+red1[4]+red1[5]) * (1.0f/kC);
    float d = v - mean;
    float q = d * d;
    #pragma unroll
    for (int o = 16; o; o >>= 1) q += __shfl_xor_sync(0xffffffffu, q, o);
    if (lane == 0) red2[wid] = q;
    __syncthreads();
    float var = (red2[0]+red2[1]+red2[2]+red2[3]+red2[4]+red2[5]) * (1.0f/kC);
    float out = d * rsqrtf(var + 1e-5f) * g[c] + bt[c];

    int wi = i >> 3, pi = i & 7, wj = j >> 3, pj = j & 7;
    int n  = (wi << 3) + wj;
    int p  = (pi << 3) + pj;
    size_t row = (size_t)((b << 6) + n) * 64 + p;
    g_hwin[row * kC + c] = out;
}

__global__ void ln2_kernel(const float* __restrict__ g,
                           const float* __restrict__ bt) {
    int t = blockIdx.x;
    int c = threadIdx.x;
    float v = g_x1[(size_t)t * kC + c];

    __shared__ float red1[6], red2[6];
    int wid = c >> 5, lane = c & 31;
    float s = v;
    #pragma unroll
    for (int o = 16; o; o >>= 1) s += __shfl_xor_sync(0xffffffffu, s, o);
    if (lane == 0) red1[wid] = s;
    __syncthreads();
    float mean = (red1[0]+red1[1]+red1[2]+red1[3]+red1[4]+red1[5]) * (1.0f/kC);
    float d = v - mean;
    float q = d * d;
    #pragma unroll
    for (int o = 16; o; o >>= 1) q += __shfl_xor_sync(0xffffffffu, q, o);
    if (lane == 0) red2[wid] = q;
    __syncthreads();
    float var = (red2[0]+red2[1]+red2[2]+red2[3]+red2[4]+red2[5]) * (1.0f/kC);
    g_h2n[(size_t)t * kC + c] = d * rsqrtf(var + 1e-5f) * g[c] + bt[c];
}

// ---------------- window-reverse + roll-back row mapping ----------------
__device__ __forceinline__ int map_row(int r) {
    int b   = r >> 12;
    int rem = r & 4095;
    int n = rem >> 6, p = rem & 63;
    int wi = n >> 3, wj = n & 7;
    int pi = p >> 3, pj = p & 7;
    int i = (wi * kP + pi + kSH) & 63;
    int j = (wj * kP + pj + kSH) & 63;
    return (((b << 6) + i) << 6) + j;
}

// ================= tf32 mma.sync GEMM, cp.async 3-stage =================
#define ASTR 20
#define BSTR 72
#define A_STAGE (128*ASTR)
#define B_STAGE (16*BSTR)
#define GEMM_SMEM ((3*A_STAGE + 3*B_STAGE) * 4)

template<int EPI>
__global__ void __launch_bounds__(128, 4) mma_gemm(
    const float* __restrict__ A, const float* __restrict__ W,
    const float* __restrict__ bias, const float* __restrict__ R,
    float* __restrict__ Co, int M, int N, int K)
{
    extern __shared__ float sm[];
    float* AsB = sm;
    float* BsB = sm + 3 * A_STAGE;

    int tid = threadIdx.x;
    int w = tid >> 5, l = tid & 31;
    int bm = blockIdx.y << 7;
    int bn = blockIdx.x << 6;

    float acc[2][8][4];
    #pragma unroll
    for (int mt = 0; mt < 2; mt++)
        #pragma unroll
        for (int nt = 0; nt < 8; nt++)
            #pragma unroll
            for (int e = 0; e < 4; e++) acc[mt][nt][e] = 0.0f;

    int a_r0 = tid >> 2;
    int a_q  = tid & 3;
    int b_k  = tid >> 4;
    int b_n4 = (tid & 15) << 2;

    int NC = K >> 4;

    auto issue = [&](int c, int buf) {
        float* As = AsB + buf * A_STAGE;
        float* Bs = BsB + buf * B_STAGE;
        int koff = c * 16;
        #pragma unroll
        for (int j = 0; j < 4; j++)
            cpa16(s2u(&As[(a_r0 + 32*j) * ASTR + a_q * 4]),
                  A + (size_t)(bm + a_r0 + 32*j) * K + koff + a_q * 4);
        cpa16(s2u(&Bs[b_k * BSTR + b_n4]),
              W + (size_t)(koff + b_k) * N + bn + b_n4);
        cpa16(s2u(&Bs[(b_k + 8) * BSTR + b_n4]),
              W + (size_t)(koff + b_k + 8) * N + bn + b_n4);
        cpa_commit();
    };

    issue(0, 0);
    issue(1, 1);

    for (int c = 0; c < NC; c++) {
        cpa_wait<1>();
        __syncthreads();
        if (c + 2 < NC) issue(c + 2, (c + 2) % 3);

        int buf = c % 3;
        const float* As = AsB + buf * A_STAGE;
        const float* Bs = BsB + buf * B_STAGE;
        #pragma unroll
        for (int s = 0; s < 2; s++) {
            int kk = s * 8 + (l & 3);
            uint32_t af[2][4];
            #pragma unroll
            for (int mt = 0; mt < 2; mt++) {
                int m = w * 32 + mt * 16 + (l >> 2);
                af[mt][0] = __float_as_uint(As[m * ASTR + kk]);
                af[mt][1] = __float_as_uint(As[(m + 8) * ASTR + kk]);
                af[mt][2] = __float_as_uint(As[m * ASTR + kk + 4]);
                af[mt][3] = __float_as_uint(As[(m + 8) * ASTR + kk + 4]);
            }
            uint32_t bf[8][2];
            #pragma unroll
            for (int nt = 0; nt < 8; nt++) {
                int n = nt * 8 + (l >> 2);
                bf[nt][0] = __float_as_uint(Bs[kk * BSTR + n]);
                bf[nt][1] = __float_as_uint(Bs[(kk + 4) * BSTR + n]);
            }
            #pragma unroll
            for (int mt = 0; mt < 2; mt++)
                #pragma unroll
                for (int nt = 0; nt < 8; nt++)
                    mma_tf32(acc[mt][nt], af[mt][0], af[mt][1], af[mt][2], af[mt][3],
                             bf[nt][0], bf[nt][1]);
        }
        __syncthreads();
    }

    #pragma unroll
    for (int mt = 0; mt < 2; mt++) {
        int r0 = bm + w * 32 + mt * 16 + (l >> 2);
        int r1 = r0 + 8;
        int o0 = (EPI == 2) ? map_row(r0) : r0;
        int o1 = (EPI == 2) ? map_row(r1) : r1;
        #pragma unroll
        for (int nt = 0; nt < 8; nt++) {
            int col = bn + nt * 8 + ((l & 3) << 1);
            float2 bb = *(const float2*)(bias + col);
            float v0 = acc[mt][nt][0] + bb.x;
            float v1 = acc[mt][nt][1] + bb.y;
            float v2 = acc[mt][nt][2] + bb.x;
            float v3 = acc[mt][nt][3] + bb.y;
            if (EPI == 1) {
                v0 = 0.5f * v0 * (1.0f + erff(v0 * 0.70710678118654752f));
                v1 = 0.5f * v1 * (1.0f + erff(v1 * 0.70710678118654752f));
                v2 = 0.5f * v2 * (1.0f + erff(v2 * 0.70710678118654752f));
                v3 = 0.5f * v3 * (1.0f + erff(v3 * 0.70710678118654752f));
            }
            if (EPI == 2 || EPI == 3) {
                float2 ra = *(const float2*)(R + (size_t)o0 * N + col);
                float2 rb = *(const float2*)(R + (size_t)o1 * N + col);
                v0 += ra.x; v1 += ra.y; v2 += rb.x; v3 += rb.y;
            }
            *(float2*)(Co + (size_t)o0 * N + col) = make_float2(v0, v1);
            *(float2*)(Co + (size_t)o1 * N + col) = make_float2(v2, v3);
        }
    }
}

// ---------------- windowed attention: tf32 mma.sync tensorized ----------------
// One block per (b, window, head). 128 threads, warp w owns rows 16w..16w+15.
// Strides: A-frag arrays ≡20 mod 32 (qs 52, sim 84); B-frag arrays ≡8 mod 32 (ks 72, vs 40).
__global__ void __launch_bounds__(128) attn_kernel() {
    __shared__ float qs[64][52];    // Q row-major [token][d]
    __shared__ float ks[32][72];    // K d-major  [d][token]
    __shared__ float vs[64][40];    // V row-major [token][f]
    __shared__ float simp[64][84];  // P row-major [token][token]

    int tid = threadIdx.x;
    int w = tid >> 5, l = tid & 31;
    int h  = blockIdx.x % kNH;
    int bn = blockIdx.x / kNH;
    int n  = bn & 63;
    size_t rowbase = (size_t)bn * 64;

    // ---- load Q,K,V ----
    #pragma unroll
    for (int it = 0; it < 4; it++) {
        int lin = tid + it * 128;          // 0..511
        int r = lin >> 3;
        int f = (lin & 7) << 2;
        const float* base = &g_qkv[(rowbase + r) * (3 * kC) + h * kHD + f];
        float4 qv = *(const float4*)(base);
        float4 kv = *(const float4*)(base + kC);
        float4 vv = *(const float4*)(base + 2 * kC);
        *(float4*)&qs[r][f] = qv;
        ks[f + 0][r] = kv.x; ks[f + 1][r] = kv.y;
        ks[f + 2][r] = kv.z; ks[f + 3][r] = kv.w;
        *(float4*)&vs[r][f] = vv;
    }
    __syncthreads();

    int m0 = w * 16;
    int qr = l >> 2;          // quad row 0..7
    int qc = l & 3;           // quad col 0..3

    // ---- S = Q @ K^T : 8 n-tiles x 4 k-steps ----
    float acc[8][4];
    #pragma unroll
    for (int nt = 0; nt < 8; nt++)
        #pragma unroll
        for (int e = 0; e < 4; e++) acc[nt][e] = 0.0f;

    #pragma unroll
    for (int s = 0; s < 4; s++) {
        int kk = s * 8 + qc;
        uint32_t a0 = __float_as_uint(qs[m0 + qr][kk]);
        uint32_t a1 = __float_as_uint(qs[m0 + 8 + qr][kk]);
        uint32_t a2 = __float_as_uint(qs[m0 + qr][kk + 4]);
        uint32_t a3 = __float_as_uint(qs[m0 + 8 + qr][kk + 4]);
        #pragma unroll
        for (int nt = 0; nt < 8; nt++) {
            int nn = nt * 8 + qr;
            uint32_t b0 = __float_as_uint(ks[kk][nn]);
            uint32_t b1 = __float_as_uint(ks[kk + 4][nn]);
            mma_tf32(acc[nt], a0, a1, a2, a3, b0, b1);
        }
    }

    // ---- scale + rel bias + shift mask (in C-fragment registers) ----
    bool lastRow = (n >> 3) == 7;
    bool lastCol = (n & 7)  == 7;
    const float scale = 0.17677669529663689f;
    int r0 = m0 + qr, r1 = r0 + 8;
    int p0i = r0 >> 3, p0j = r0 & 7;
    int p1i = r1 >> 3, p1j = r1 & 7;

    float mx0 = -1e30f, mx1 = -1e30f;
    #pragma unroll
    for (int nt = 0; nt < 8; nt++) {
        int c0 = nt * 8 + qc * 2;
        float2 bb0 = *(const float2*)&g_btab[h * 4096 + r0 * 64 + c0];
        float2 bb1 = *(const float2*)&g_btab[h * 4096 + r1 * 64 + c0];
        #pragma unroll
        for (int e = 0; e < 2; e++) {
            int q = c0 + e;
            int qi = q >> 3, qj = q & 7;
            float v0 = acc[nt][e]     * scale + (e ? bb0.y : bb0.x);
            float v1 = acc[nt][e + 2] * scale + (e ? bb1.y : bb1.x);
            bool m0b = (lastRow && ((p0i < 4) != (qi < 4))) ||
                       (lastCol && ((p0j < 4) != (qj < 4)));
            bool m1b = (lastRow && ((p1i < 4) != (qi < 4))) ||
                       (lastCol && ((p1j < 4) != (qj < 4)));
            v0 = m0b ? -1e30f : v0;
            v1 = m1b ? -1e30f : v1;
            acc[nt][e]     = v0;
            acc[nt][e + 2] = v1;
            mx0 = fmaxf(mx0, v0);
            mx1 = fmaxf(mx1, v1);
        }
    }
    // row reductions across the 4-lane quad
    mx0 = fmaxf(mx0, __shfl_xor_sync(0xffffffffu, mx0, 1));
    mx0 = fmaxf(mx0, __shfl_xor_sync(0xffffffffu, mx0, 2));
    mx1 = fmaxf(mx1, __shfl_xor_sync(0xffffffffu, mx1, 1));
    mx1 = fmaxf(mx1, __shfl_xor_sync(0xffffffffu, mx1, 2));

    float sum0 = 0.0f, sum1 = 0.0f;
    #pragma unroll
    for (int nt = 0; nt < 8; nt++) {
        float e0 = __expf(acc[nt][0] - mx0);
        float e1 = __expf(acc[nt][1] - mx0);
        float e2 = __expf(acc[nt][2] - mx1);
        float e3 = __expf(acc[nt][3] - mx1);
        acc[nt][0] = e0; acc[nt][1] = e1; acc[nt][2] = e2; acc[nt][3] = e3;
        sum0 += e0 + e1;
        sum1 += e2 + e3;
    }
    sum0 += __shfl_xor_sync(0xffffffffu, sum0, 1);
    sum0 += __shfl_xor_sync(0xffffffffu, sum0, 2);
    sum1 += __shfl_xor_sync(0xffffffffu, sum1, 1);
    sum1 += __shfl_xor_sync(0xffffffffu, sum1, 2);
    float inv0 = 1.0f / sum0, inv1 = 1.0f / sum1;

    // write P to smem for PV A-fragments
    #pragma unroll
    for (int nt = 0; nt < 8; nt++) {
        int c0 = nt * 8 + qc * 2;
        *(float2*)&simp[r0][c0] = make_float2(acc[nt][0] * inv0, acc[nt][1] * inv0);
        *(float2*)&simp[r1][c0] = make_float2(acc[nt][2] * inv1, acc[nt][3] * inv1);
    }
    __syncthreads();

    // ---- O = P @ V : 4 n-tiles x 8 k-steps ----
    float oacc[4][4];
    #pragma unroll
    for (int nt = 0; nt < 4; nt++)
        #pragma unroll
        for (int e = 0; e < 4; e++) oacc[nt][e] = 0.0f;

    #pragma unroll
    for (int s = 0; s < 8; s++) {
        int kk = s * 8 + qc;
        uint32_t a0 = __float_as_uint(simp[m0 + qr][kk]);
        uint32_t a1 = __float_as_uint(simp[m0 + 8 + qr][kk]);
        uint32_t a2 = __float_as_uint(simp[m0 + qr][kk + 4]);
        uint32_t a3 = __float_as_uint(simp[m0 + 8 + qr][kk + 4]);
        #pragma unroll
        for (int nt = 0; nt < 4; nt++) {
            int nn = nt * 8 + qr;
            uint32_t b0 = __float_as_uint(vs[kk][nn]);
            uint32_t b1 = __float_as_uint(vs[kk + 4][nn]);
            mma_tf32(oacc[nt], a0, a1, a2, a3, b0, b1);
        }
    }

    // ---- write O ----
    float* d0 = &g_attn[(rowbase + r0) * kC + h * kHD];
    float* d1 = &g_attn[(rowbase + r1) * kC + h * kHD];
    #pragma unroll
    for (int nt = 0; nt < 4; nt++) {
        int c0 = nt * 8 + qc * 2;
        *(float2*)(d0 + c0) = make_float2(oacc[nt][0], oacc[nt][1]);
        *(float2*)(d1 + c0) = make_float2(oacc[nt][2], oacc[nt][3]);
    }
}

// ---------------- launch ----------------
extern "C" void kernel_launch(void* const* d_in, const int* in_sizes, int n_in,
                              void* d_out, int out_size) {
    const float* x      = (const float*)d_in[0];
    const float* g1     = (const float*)d_in[1];
    const float* b1     = (const float*)d_in[2];
    const float* w_qkv  = (const float*)d_in[3];
    const float* b_qkv  = (const float*)d_in[4];
    const float* relp   = (const float*)d_in[5];
    const float* w_proj = (const float*)d_in[6];
    const float* b_proj = (const float*)d_in[7];
    const float* g2     = (const float*)d_in[8];
    const float* b2     = (const float*)d_in[9];
    const float* w_mlp1 = (const float*)d_in[10];
    const float* b_mlp1 = (const float*)d_in[11];
    const float* w_mlp2 = (const float*)d_in[12];
    const float* b_mlp2 = (const float*)d_in[13];
    float* out = (float*)d_out;

    float *hwin, *qkvb, *attnb, *x1, *h2n, *mid;
    cudaGetSymbolAddress((void**)&hwin,  g_hwin);
    cudaGetSymbolAddress((void**)&qkvb,  g_qkv);
    cudaGetSymbolAddress((void**)&attnb, g_attn);
    cudaGetSymbolAddress((void**)&x1,    g_x1);
    cudaGetSymbolAddress((void**)&h2n,   g_h2n);
    cudaGetSymbolAddress((void**)&mid,   g_mid);

    // 1. relative-position bias table
    btab_kernel<<<(kNH * kPP * kPP + 255) / 256, 256>>>(relp);
    // 2. LN1 + roll + window partition
    ln1_kernel<<<kTOK, kC>>>(x, g1, b1);
    // 3. QKV GEMM: [65536,192] @ [192,576]
    mma_gemm<0><<<dim3(576 / 64, kTOK / 128), 128, GEMM_SMEM>>>(
        hwin, w_qkv, b_qkv, nullptr, qkvb, kTOK, 576, kC);
    // 4. windowed attention (tensorized)
    attn_kernel<<<kB * kNW * kNH, 128>>>();
    // 5. proj GEMM + window-reverse + roll-back + residual
    mma_gemm<2><<<dim3(kC / 64, kTOK / 128), 128, GEMM_SMEM>>>(
        attnb, w_proj, b_proj, x, x1, kTOK, kC, kC);
    // 6. LN2
    ln2_kernel<<<kTOK, kC>>>(g2, b2);
    // 7. MLP1 + GELU
    mma_gemm<1><<<dim3(768 / 64, kTOK / 128), 128, GEMM_SMEM>>>(
        h2n, w_mlp1, b_mlp1, nullptr, mid, kTOK, 768, kC);
    // 8. MLP2 + residual -> out
    mma_gemm<3><<<dim3(kC / 64, kTOK / 128), 128, GEMM_SMEM>>>(
        mid, w_mlp2, b_mlp2, x1, out, kTOK, kC, 768);
}